// round 15
// baseline (speedup 1.0000x reference)
#include <cuda_runtime.h>
#include <cuda_fp16.h>
#include <math.h>
#include <stdint.h>

// Problem constants
#define Bn 4
#define Sn 2048
#define DIMn 1024
#define Hn 16
#define Dn 64
#define Tn (Bn*Sn)      // 8192 tokens
#define HDn 1024
#define WIN 512

typedef unsigned short ush;

// ---------------------------------------------------------------------------
// Scratch (device globals)
// ---------------------------------------------------------------------------
__device__ float g_mix[Tn*Hn];
__device__ float g_gate[Tn*Hn];
__device__ float2 g_rope[Sn*32];          // (cos, sin) per (s, i)

__device__ ush g_tok[(size_t)Tn*DIMn];    // fp16 tokens
__device__ ush g_ao[(size_t)Tn*HDn];      // fp16 attention output
__device__ ush g_wallh[3072*1024];        // fp16: [Wq|Wk|Wv]^T [N=3072,K=1024]
__device__ ush g_woh[1024*1024];          // fp16: Wout^T
__device__ ush g_qs[(size_t)Tn*HDn];      // fp16 q (post-rope, scaled by 0.125*log2e)
__device__ ush g_ks[(size_t)Tn*HDn];      // fp16 k (post-rope)
__device__ ush g_vs[(size_t)Tn*HDn];      // fp16 v (post-mix)

// ---------------------------------------------------------------------------
// Helpers (base sm_103 target — mma.sync / ldmatrix / cp.async, NO tcgen05)
// ---------------------------------------------------------------------------
__device__ __forceinline__ uint32_t smem_u32(const void* p) {
    uint32_t a;
    asm("{ .reg .u64 t; cvta.to.shared.u64 t, %1; cvt.u32.u64 %0, t; }" : "=r"(a) : "l"(p));
    return a;
}
__device__ __forceinline__ void ldsm4(uint32_t* r, uint32_t addr) {
    asm volatile("ldmatrix.sync.aligned.m8n8.x4.shared.b16 {%0,%1,%2,%3}, [%4];"
                 : "=r"(r[0]), "=r"(r[1]), "=r"(r[2]), "=r"(r[3]) : "r"(addr));
}
__device__ __forceinline__ void ldsm4t(uint32_t* r, uint32_t addr) {
    asm volatile("ldmatrix.sync.aligned.m8n8.x4.trans.shared.b16 {%0,%1,%2,%3}, [%4];"
                 : "=r"(r[0]), "=r"(r[1]), "=r"(r[2]), "=r"(r[3]) : "r"(addr));
}
__device__ __forceinline__ void mma16816h(float* d, const uint32_t* a, const uint32_t* b) {
    asm volatile("mma.sync.aligned.m16n8k16.row.col.f32.f16.f16.f32 "
                 "{%0,%1,%2,%3},{%4,%5,%6,%7},{%8,%9},{%0,%1,%2,%3};"
                 : "+f"(d[0]), "+f"(d[1]), "+f"(d[2]), "+f"(d[3])
                 : "r"(a[0]), "r"(a[1]), "r"(a[2]), "r"(a[3]),
                   "r"(b[0]), "r"(b[1]));
}
__device__ __forceinline__ void cp16(uint32_t smem, const void* g) {
    asm volatile("cp.async.cg.shared.global [%0], [%1], 16;" :: "r"(smem), "l"(g));
}
__device__ __forceinline__ uint32_t packh(float y0, float y1) {
    __half2 h = __floats2half2_rn(y0, y1);
    return *reinterpret_cast<uint32_t*>(&h);
}

// ---------------------------------------------------------------------------
// Fused prep kernel: conv1 | convW x3 | mixgate | rope table
// ---------------------------------------------------------------------------
#define NB_CONV1 (Tn*DIMn/4/256)   // 8192
#define NB_WQ   1024
#define NB_WKV  2048
#define NB_WO   1024
#define NB_MIX  64
#define NB_TAB  (Sn*32/256)        // 256
#define NB_PREP (NB_CONV1+NB_WQ+NB_WKV+NB_WO+NB_MIX+NB_TAB)
#define PREP_SMEM (128*65*4 + 64*32*4)

__global__ void __launch_bounds__(256) prep(
    const float* __restrict__ tokens,
    const float* __restrict__ Wq, const float* __restrict__ Wkv,
    const float* __restrict__ Wout,
    const float* __restrict__ Wmix, const float* __restrict__ Wgate,
    ush* __restrict__ tok, ush* __restrict__ wall, ush* __restrict__ wo,
    float* __restrict__ gmix, float* __restrict__ ggate,
    float2* __restrict__ rope)
{
    extern __shared__ char ps[];
    int blk = blockIdx.x;
    const int tid = threadIdx.x;

    if (blk < NB_CONV1) {
        int i = blk * 256 + tid;
        float4 v = ((const float4*)tokens)[i];
        ((uint2*)tok)[i] = make_uint2(packh(v.x, v.y), packh(v.z, v.w));
        return;
    }
    blk -= NB_CONV1;

    if (blk < NB_WQ + NB_WKV + NB_WO) {
        const float* W; ush* T; int N;
        if (blk < NB_WQ)               { W = Wq;   T = wall;               N = 1024; }
        else if (blk < NB_WQ + NB_WKV) { W = Wkv;  T = wall + 1024 * 1024; N = 2048; blk -= NB_WQ; }
        else                           { W = Wout; T = wo;                 N = 1024; blk -= NB_WQ + NB_WKV; }
        float (*t)[33] = (float(*)[33])ps;
        int ntiles = N / 32;
        int n0 = (blk % ntiles) * 32, k0 = (blk / ntiles) * 32;
        int tx = tid & 31, ty = tid >> 5;
#pragma unroll
        for (int r = 0; r < 4; r++)
            t[ty + 8 * r][tx] = W[(size_t)(k0 + ty + 8 * r) * N + n0 + tx];
        __syncthreads();
#pragma unroll
        for (int r = 0; r < 4; r++) {
            float v = t[tx][ty + 8 * r];
            __half hb = __float2half_rn(v);
            T[(size_t)(n0 + ty + 8 * r) * 1024 + k0 + tx] = *reinterpret_cast<ush*>(&hb);
        }
        return;
    }
    blk -= NB_WQ + NB_WKV + NB_WO;

    if (blk < NB_MIX) {
        float* Ts = (float*)ps;
        float* Ws = Ts + 128 * 65;
        const int row0 = blk * 128;
        const int r  = tid >> 1;
        const int cg = (tid & 1) << 4;

        float acc[16];
#pragma unroll
        for (int c = 0; c < 16; c++) acc[c] = 0.f;

        for (int k0 = 0; k0 < 1024; k0 += 64) {
#pragma unroll
            for (int u = 0; u < 8; u++) {
                int fi = tid + u * 256;
                int rr = fi >> 4;
                int cc = (fi & 15) << 2;
                float4 x = *(const float4*)(tokens + (size_t)(row0 + rr) * 1024 + k0 + cc);
                Ts[rr * 65 + cc]     = x.x;
                Ts[rr * 65 + cc + 1] = x.y;
                Ts[rr * 65 + cc + 2] = x.z;
                Ts[rr * 65 + cc + 3] = x.w;
            }
#pragma unroll
            for (int u = 0; u < 8; u++) {
                int fi = tid + u * 256;
                int rr = fi >> 5;
                int cc = fi & 31;
                Ws[rr * 32 + cc] = (cc < 16) ? Wmix[(k0 + rr) * 16 + cc]
                                             : Wgate[(k0 + rr) * 16 + (cc - 16)];
            }
            __syncthreads();
            for (int kk = 0; kk < 64; kk++) {
                float a = Ts[r * 65 + kk];
#pragma unroll
                for (int c = 0; c < 16; c++) acc[c] += a * Ws[kk * 32 + cg + c];
            }
            __syncthreads();
        }

        const int t = row0 + r;
#pragma unroll
        for (int c = 0; c < 16; c++) {
            float sg = 1.0f / (1.0f + expf(-acc[c]));
            int col = cg + c;
            if (col < 16) gmix[t * 16 + col] = sg;
            else          ggate[t * 16 + (col - 16)] = sg;
        }
        return;
    }
    blk -= NB_MIX;

    {
        const float L2F = 13.2877123795494f / 32.0f;
        int idx = blk * 256 + tid;
        int s = idx >> 5, i = idx & 31;
        float inv = exp2f(-(float)i * L2F);
        float ang = (float)s * inv;
        float sn, cs;
        sincosf(ang, &sn, &cs);
        rope[idx] = make_float2(cs, sn);
    }
}

// ---------------------------------------------------------------------------
// fp16 GEMM: C = A @ B^T. CTA 128x256, 256 thr, 8 warps (2m x 4n),
// warp tile 64x64 (acc 128 regs), K-chunk 64, 3-stage cp.async, 1 CTA/SM.
// mode 0: fp32 C store. mode 1: fused QKV epilogue (rope table / v-mix).
// ---------------------------------------------------------------------------
#define PADE 72
#define A_ELEMS (128*PADE)                // 9216
#define B_ELEMS (256*PADE)                // 18432
#define STAGE_ELEMS (A_ELEMS+B_ELEMS)     // 27648 (55296 B)
#define NSTAGE 3
#define NCHUNK 16
#define GEMM_SMEM (NSTAGE*STAGE_ELEMS*2)  // 165888 B

__global__ void __launch_bounds__(256, 1) gemm_mma(
    const ush* __restrict__ Ah, const ush* __restrict__ Bh,
    float* __restrict__ C,
    ush* __restrict__ qs, ush* __restrict__ ks, ush* __restrict__ vs,
    const float* __restrict__ vres, const float* __restrict__ mix,
    const float2* __restrict__ rope,
    int mode)
{
    extern __shared__ ush sh[];
    const int tid  = threadIdx.x;
    const int wid  = tid >> 5, lane = tid & 31;
    const int brow = blockIdx.y * 128, bcol = blockIdx.x * 256;
    const int wm   = (wid & 1) * 64;      // 2 m-warps
    const int wn   = (wid >> 1) * 64;     // 4 n-warps
    const int K    = 1024;

    const uint32_t sbase = smem_u32(sh);

    float acc[4][8][4];
#pragma unroll
    for (int i = 0; i < 4; i++)
#pragma unroll
        for (int j = 0; j < 8; j++)
#pragma unroll
            for (int k = 0; k < 4; k++) acc[i][j][k] = 0.f;

    auto cp_chunk = [&](int cidx) {
        int k0 = cidx * 64;
        uint32_t st = (uint32_t)(cidx % NSTAGE) * STAGE_ELEMS * 2;
        // A: 128 rows x 64 cols = 1024 x 16B
#pragma unroll
        for (int q = 0; q < 4; q++) {
            int e = tid + q * 256;
            int row = e >> 3, ce = (e & 7) * 8;
            cp16(sbase + st + (uint32_t)(row * PADE + ce) * 2,
                 Ah + (size_t)(brow + row) * K + k0 + ce);
        }
        // B: 256 rows x 64 cols = 2048 x 16B
#pragma unroll
        for (int q = 0; q < 8; q++) {
            int e = tid + q * 256;
            int row = e >> 3, ce = (e & 7) * 8;
            cp16(sbase + st + (uint32_t)(A_ELEMS + row * PADE + ce) * 2,
                 Bh + (size_t)(bcol + row) * K + k0 + ce);
        }
        asm volatile("cp.async.commit_group;" ::: "memory");
    };

    cp_chunk(0); cp_chunk(1);

    for (int c = 0; c < NCHUNK; c++) {
        asm volatile("cp.async.wait_group 1;" ::: "memory");
        __syncthreads();
        if (c + 2 < NCHUNK) cp_chunk(c + 2);
        else asm volatile("cp.async.commit_group;" ::: "memory");

        uint32_t abase = sbase + (uint32_t)(c % NSTAGE) * STAGE_ELEMS * 2;

#pragma unroll
        for (int ksub = 0; ksub < 4; ksub++) {
            uint32_t a[4][4];
            {
                int arow = wm + (lane & 15);
                int acol = ksub * 16 + (lane >> 4) * 8;
#pragma unroll
                for (int ms = 0; ms < 4; ms++)
                    ldsm4(a[ms], abase + (uint32_t)((arow + ms * 16) * PADE + acol) * 2);
            }
            uint32_t b[8][2];
            {
                int bn = (lane & 7) | ((lane >> 1) & 8);
                int bk = ksub * 16 + ((lane >> 3) & 1) * 8;
#pragma unroll
                for (int g = 0; g < 4; g++) {
                    uint32_t r[4];
                    ldsm4(r, abase + (uint32_t)(A_ELEMS +
                          (wn + g * 16 + bn) * PADE + bk) * 2);
                    b[2 * g][0]     = r[0]; b[2 * g][1]     = r[1];
                    b[2 * g + 1][0] = r[2]; b[2 * g + 1][1] = r[3];
                }
            }
#pragma unroll
            for (int ms = 0; ms < 4; ms++)
#pragma unroll
                for (int nf = 0; nf < 8; nf++)
                    mma16816h(acc[ms][nf], a[ms], b[nf]);
        }
        __syncthreads();
    }

    if (mode == 0) {
#pragma unroll
        for (int ms = 0; ms < 4; ms++) {
            int r0 = brow + wm + ms * 16 + (lane >> 2);
#pragma unroll
            for (int nf = 0; nf < 8; nf++) {
                int cc = bcol + wn + nf * 8 + 2 * (lane & 3);
                *(float2*)(C + (size_t)r0 * 1024 + cc)       = make_float2(acc[ms][nf][0], acc[ms][nf][1]);
                *(float2*)(C + (size_t)(r0 + 8) * 1024 + cc) = make_float2(acc[ms][nf][2], acc[ms][nf][3]);
            }
        }
        return;
    }

    // fused QKV epilogue: seg 0=q (rope, scale 0.125*log2e), 1=k (rope), 2=v (mix)
    const int seg  = bcol >> 10;
    const int colb = (bcol & 1023) + wn + 2 * (lane & 3);
    ush* dst = (seg == 0) ? qs : (seg == 1) ? ks : vs;
    const float qscale = (seg == 0) ? 0.125f * 1.4426950408889634f : 1.0f;

#pragma unroll
    for (int ms = 0; ms < 4; ms++) {
        int r0 = brow + wm + ms * 16 + (lane >> 2);
#pragma unroll
        for (int half = 0; half < 2; half++) {
            int row = r0 + half * 8;
            int s = row & (Sn - 1);
            int bb = row >> 11;
#pragma unroll
            for (int nf = 0; nf < 8; nf++) {
                float x0 = acc[ms][nf][half * 2 + 0];
                float x1 = acc[ms][nf][half * 2 + 1];
                int colc = colb + nf * 8;
                size_t o = (size_t)row * 1024 + colc;
                float y0, y1;
                if (seg < 2) {
                    int i = (colc & 63) >> 1;
                    float2 t = rope[(s << 5) + i];
                    y0 = (x0 * t.x - x1 * t.y) * qscale;
                    y1 = (x1 * t.x + x0 * t.y) * qscale;
                } else {
                    int hh = (colc & 1023) >> 6;
                    int d  = colc & 63;
                    float m = mix[row * Hn + hh];
                    const float* rp = vres + (((size_t)bb * Hn + hh) * Sn + s) * Dn + d;
                    float2 rr = *(const float2*)rp;
                    y0 = x0 + (rr.x - x0) * m;
                    y1 = x1 + (rr.y - x1) * m;
                }
                *(uint32_t*)(dst + o) = packh(y0, y1);
            }
        }
    }
}

// ---------------------------------------------------------------------------
// Sliding-window flash attention, fp16, exp2-domain softmax,
// cp.async double-buffered K/V tiles.
// ---------------------------------------------------------------------------
#define APAD 72
#define AARR (64*APAD)
#define ATT_SMEM (5*AARR*2)   // Q, K0, V0, K1, V1

__global__ void __launch_bounds__(128) attn_mma(
    const ush* __restrict__ qs, const ush* __restrict__ kh,
    const ush* __restrict__ vh, const float* __restrict__ gate,
    ush* __restrict__ ao)
{
    extern __shared__ ush smA[];
    ush* Qs = smA;

    const int b = blockIdx.z, h = blockIdx.y, q0 = blockIdx.x * 64;
    const int tid = threadIdx.x, wid = tid >> 5, lane = tid & 31;
    const int wm = wid * 16;
    const size_t bbase = (size_t)b * Sn;
    const int hoff = h * Dn;

    const uint32_t sb = smem_u32(Qs);
    const int jt_lo = (q0 >= WIN) ? ((q0 - WIN) >> 6) : 0;
    const int jt_hi = q0 >> 6;

    auto cp_kv = [&](int jt, int buf) {
        int j0 = jt * 64;
        const ush* kg = kh + (bbase + j0) * (size_t)HDn + hoff;
        const ush* vg = vh + (bbase + j0) * (size_t)HDn + hoff;
        uint32_t kd = sb + (uint32_t)((1 + 2 * buf) * AARR) * 2;
        uint32_t vd = kd + (uint32_t)AARR * 2;
#pragma unroll
        for (int i = 0; i < 4; i++) {
            int e = tid + i * 128;
            int row = e >> 3, c = (e & 7) * 8;
            cp16(kd + (uint32_t)(row * APAD + c) * 2, kg + (size_t)row * HDn + c);
            cp16(vd + (uint32_t)(row * APAD + c) * 2, vg + (size_t)row * HDn + c);
        }
        asm volatile("cp.async.commit_group;" ::: "memory");
    };

    cp_kv(jt_lo, 0);
#pragma unroll
    for (int i = 0; i < 4; i++) {
        int e = tid + i * 128;
        int row = e >> 3, c = (e & 7) * 8;
        size_t g = (bbase + q0 + row) * (size_t)HDn + hoff + c;
        *(uint4*)(Qs + row * APAD + c) = *(const uint4*)(qs + g);
    }
    __syncthreads();

    uint32_t qf[4][4];
    {
        int arow = wm + (lane & 15);
        int ac0  = (lane >> 4) * 8;
#pragma unroll
        for (int ks = 0; ks < 4; ks++)
            ldsm4(qf[ks], sb + (uint32_t)(arow * APAD + ks * 16 + ac0) * 2);
    }

    float mi0 = -1e30f, mi1 = -1e30f, li0 = 0.f, li1 = 0.f;
    float accO[8][4];
#pragma unroll
    for (int i = 0; i < 8; i++)
#pragma unroll
        for (int j = 0; j < 4; j++) accO[i][j] = 0.f;

    const int gi0 = q0 + wm + (lane >> 2);
    const int gi1 = gi0 + 8;

    const int bn  = (lane & 7) | ((lane >> 1) & 8);
    const int bk8 = ((lane >> 3) & 1) * 8;
    const int vr0 = lane & 15;
    const int vc8 = (lane >> 4) * 8;

    for (int jt = jt_lo; jt <= jt_hi; jt++) {
        const int j0 = jt * 64;
        const int buf = (jt - jt_lo) & 1;
        asm volatile("cp.async.wait_group 0;" ::: "memory");
        __syncthreads();
        if (jt < jt_hi) cp_kv(jt + 1, buf ^ 1);

        const uint32_t kb = sb + (uint32_t)((1 + 2 * buf) * AARR) * 2;
        const uint32_t vb = kb + (uint32_t)AARR * 2;

        float s[8][4];
#pragma unroll
        for (int i = 0; i < 8; i++)
#pragma unroll
            for (int j = 0; j < 4; j++) s[i][j] = 0.f;

#pragma unroll
        for (int ks = 0; ks < 4; ks++) {
#pragma unroll
            for (int g2 = 0; g2 < 4; g2++) {
                uint32_t off = (uint32_t)(((g2 * 16 + bn) * APAD + ks * 16 + bk8) * 2);
                uint32_t rh[4];
                ldsm4(rh, kb + off);
                uint32_t bh0[2] = {rh[0], rh[1]}, bh1[2] = {rh[2], rh[3]};
                mma16816h(s[2*g2],   qf[ks], bh0);
                mma16816h(s[2*g2+1], qf[ks], bh1);
            }
        }

        if (jt == jt_hi || (jt == jt_lo && q0 >= WIN)) {
#pragma unroll
            for (int nf = 0; nf < 8; nf++) {
                int cbase = j0 + nf * 8 + (lane & 3) * 2;
#pragma unroll
                for (int jj = 0; jj < 2; jj++) {
                    int gj = cbase + jj;
                    int d0 = gi0 - gj, d1 = gi1 - gj;
                    if (d0 < 0 || d0 > WIN) s[nf][jj]     = -1e30f;
                    if (d1 < 0 || d1 > WIN) s[nf][2 + jj] = -1e30f;
                }
            }
        }

        float mt0 = -1e30f, mt1 = -1e30f;
#pragma unroll
        for (int nf = 0; nf < 8; nf++) {
            mt0 = fmaxf(mt0, fmaxf(s[nf][0], s[nf][1]));
            mt1 = fmaxf(mt1, fmaxf(s[nf][2], s[nf][3]));
        }
        mt0 = fmaxf(mt0, __shfl_xor_sync(0xffffffffu, mt0, 1));
        mt0 = fmaxf(mt0, __shfl_xor_sync(0xffffffffu, mt0, 2));
        mt1 = fmaxf(mt1, __shfl_xor_sync(0xffffffffu, mt1, 1));
        mt1 = fmaxf(mt1, __shfl_xor_sync(0xffffffffu, mt1, 2));

        float mn0 = fmaxf(mi0, mt0), mn1 = fmaxf(mi1, mt1);
        float f0 = exp2f(mi0 - mn0), f1 = exp2f(mi1 - mn1);
        mi0 = mn0; mi1 = mn1;

        float su0 = 0.f, su1 = 0.f;
#pragma unroll
        for (int nf = 0; nf < 8; nf++) {
            s[nf][0] = exp2f(s[nf][0] - mn0);
            s[nf][1] = exp2f(s[nf][1] - mn0);
            s[nf][2] = exp2f(s[nf][2] - mn1);
            s[nf][3] = exp2f(s[nf][3] - mn1);
            su0 += s[nf][0] + s[nf][1];
            su1 += s[nf][2] + s[nf][3];
        }
        su0 += __shfl_xor_sync(0xffffffffu, su0, 1);
        su0 += __shfl_xor_sync(0xffffffffu, su0, 2);
        su1 += __shfl_xor_sync(0xffffffffu, su1, 1);
        su1 += __shfl_xor_sync(0xffffffffu, su1, 2);
        li0 = li0 * f0 + su0;
        li1 = li1 * f1 + su1;
#pragma unroll
        for (int nf = 0; nf < 8; nf++) {
            accO[nf][0] *= f0; accO[nf][1] *= f0;
            accO[nf][2] *= f1; accO[nf][3] *= f1;
        }

#pragma unroll
        for (int ks = 0; ks < 4; ks++) {
            uint32_t ph[4];
            const float* p0 = s[2 * ks];
            const float* p1 = s[2 * ks + 1];
            ph[0] = packh(p0[0], p0[1]);
            ph[1] = packh(p0[2], p0[3]);
            ph[2] = packh(p1[0], p1[1]);
            ph[3] = packh(p1[2], p1[3]);
#pragma unroll
            for (int g2 = 0; g2 < 4; g2++) {
                uint32_t off = (uint32_t)(((ks * 16 + vr0) * APAD + g2 * 16 + vc8) * 2);
                uint32_t rh[4];
                ldsm4t(rh, vb + off);
                uint32_t bh0[2] = {rh[0], rh[1]}, bh1[2] = {rh[2], rh[3]};
                mma16816h(accO[2*g2],   ph, bh0);
                mma16816h(accO[2*g2+1], ph, bh1);
            }
        }
    }

    float g0 = gate[(bbase + gi0) * Hn + h];
    float g1 = gate[(bbase + gi1) * Hn + h];
    float sc0 = g0 / li0, sc1 = g1 / li1;
#pragma unroll
    for (int nf = 0; nf < 8; nf++) {
        int col = hoff + nf * 8 + (lane & 3) * 2;
        size_t i0 = (bbase + gi0) * (size_t)HDn + col;
        size_t i1 = (bbase + gi1) * (size_t)HDn + col;
        *(uint32_t*)(ao + i0) = packh(accO[nf][0] * sc0, accO[nf][1] * sc0);
        *(uint32_t*)(ao + i1) = packh(accO[nf][2] * sc1, accO[nf][3] * sc1);
    }
}

// ---------------------------------------------------------------------------
extern "C" void kernel_launch(void* const* d_in, const int* in_sizes, int n_in,
                              void* d_out, int out_size)
{
    const float* tokens = (const float*)d_in[0];
    const float* vres   = (const float*)d_in[1];
    const float* Wq     = (const float*)d_in[2];
    const float* Wkv    = (const float*)d_in[3];
    const float* Wout   = (const float*)d_in[4];
    const float* Wgate  = (const float*)d_in[5];
    const float* Wmix   = (const float*)d_in[6];
    float* out = (float*)d_out;

    float *pmix, *pgate;
    float2* prope;
    ush *tk, *ao, *wah, *woh, *qsp, *ksp, *vsp;
    cudaGetSymbolAddress((void**)&pmix, g_mix);
    cudaGetSymbolAddress((void**)&pgate,g_gate);
    cudaGetSymbolAddress((void**)&prope,g_rope);
    cudaGetSymbolAddress((void**)&tk,   g_tok);
    cudaGetSymbolAddress((void**)&ao,   g_ao);
    cudaGetSymbolAddress((void**)&wah,  g_wallh);
    cudaGetSymbolAddress((void**)&woh,  g_woh);
    cudaGetSymbolAddress((void**)&qsp,  g_qs);
    cudaGetSymbolAddress((void**)&ksp,  g_ks);
    cudaGetSymbolAddress((void**)&vsp,  g_vs);

    cudaFuncSetAttribute(prep,     cudaFuncAttributeMaxDynamicSharedMemorySize, PREP_SMEM);
    cudaFuncSetAttribute(gemm_mma, cudaFuncAttributeMaxDynamicSharedMemorySize, GEMM_SMEM);
    cudaFuncSetAttribute(attn_mma, cudaFuncAttributeMaxDynamicSharedMemorySize, ATT_SMEM);

    // 1. fused prep: token cast + weight transposes + mix/gate + rope table
    prep<<<NB_PREP, 256, PREP_SMEM>>>(tokens, Wq, Wkv, Wout, Wmix, Wgate,
                                      tk, wah, woh, pmix, pgate, prope);

    // 2. merged QKV projection with fused rope / v-mix epilogue (CTA 128x256)
    gemm_mma<<<dim3(12, 64), 256, GEMM_SMEM>>>(
        tk, wah, nullptr, qsp, ksp, vsp, vres, pmix, prope, 1);

    // 3. windowed attention (fp16, exp2 softmax, pipelined K/V) + gate
    attn_mma<<<dim3(Sn / 64, Hn, Bn), 128, ATT_SMEM>>>(
        qsp, ksp, vsp, pgate, ao);

    // 4. output projection into d_out
    gemm_mma<<<dim3(4, 64), 256, GEMM_SMEM>>>(
        ao, woh, out, nullptr, nullptr, nullptr, nullptr, nullptr, nullptr, 0);
}

// round 16
// speedup vs baseline: 1.0577x; 1.0577x over previous
#include <cuda_runtime.h>
#include <cuda_fp16.h>
#include <math.h>
#include <stdint.h>

// Problem constants
#define Bn 4
#define Sn 2048
#define DIMn 1024
#define Hn 16
#define Dn 64
#define Tn (Bn*Sn)      // 8192 tokens
#define HDn 1024
#define WIN 512

typedef unsigned short ush;

// ---------------------------------------------------------------------------
// Scratch (device globals)
// ---------------------------------------------------------------------------
__device__ float g_mix[Tn*Hn];
__device__ float g_gate[Tn*Hn];
__device__ float2 g_rope[Sn*32];          // (cos, sin) per (s, i)

__device__ ush g_tok[(size_t)Tn*DIMn];    // fp16 tokens
__device__ ush g_ao[(size_t)Tn*HDn];      // fp16 attention output
__device__ ush g_wallh[3072*1024];        // fp16: [Wq|Wk|Wv]^T [N=3072,K=1024]
__device__ ush g_woh[1024*1024];          // fp16: Wout^T
__device__ ush g_qs[(size_t)Tn*HDn];      // fp16 q (post-rope, scaled by 0.125*log2e)
__device__ ush g_ks[(size_t)Tn*HDn];      // fp16 k (post-rope)
__device__ ush g_vs[(size_t)Tn*HDn];      // fp16 v (post-mix)

// ---------------------------------------------------------------------------
// Helpers (base sm_103 target — mma.sync / ldmatrix / cp.async, NO tcgen05)
// ---------------------------------------------------------------------------
__device__ __forceinline__ uint32_t smem_u32(const void* p) {
    uint32_t a;
    asm("{ .reg .u64 t; cvta.to.shared.u64 t, %1; cvt.u32.u64 %0, t; }" : "=r"(a) : "l"(p));
    return a;
}
__device__ __forceinline__ void ldsm4(uint32_t* r, uint32_t addr) {
    asm volatile("ldmatrix.sync.aligned.m8n8.x4.shared.b16 {%0,%1,%2,%3}, [%4];"
                 : "=r"(r[0]), "=r"(r[1]), "=r"(r[2]), "=r"(r[3]) : "r"(addr));
}
__device__ __forceinline__ void ldsm4t(uint32_t* r, uint32_t addr) {
    asm volatile("ldmatrix.sync.aligned.m8n8.x4.trans.shared.b16 {%0,%1,%2,%3}, [%4];"
                 : "=r"(r[0]), "=r"(r[1]), "=r"(r[2]), "=r"(r[3]) : "r"(addr));
}
__device__ __forceinline__ void mma16816h(float* d, const uint32_t* a, const uint32_t* b) {
    asm volatile("mma.sync.aligned.m16n8k16.row.col.f32.f16.f16.f32 "
                 "{%0,%1,%2,%3},{%4,%5,%6,%7},{%8,%9},{%0,%1,%2,%3};"
                 : "+f"(d[0]), "+f"(d[1]), "+f"(d[2]), "+f"(d[3])
                 : "r"(a[0]), "r"(a[1]), "r"(a[2]), "r"(a[3]),
                   "r"(b[0]), "r"(b[1]));
}
__device__ __forceinline__ void cp16(uint32_t smem, const void* g) {
    asm volatile("cp.async.cg.shared.global [%0], [%1], 16;" :: "r"(smem), "l"(g));
}
__device__ __forceinline__ uint32_t packh(float y0, float y1) {
    __half2 h = __floats2half2_rn(y0, y1);
    return *reinterpret_cast<uint32_t*>(&h);
}

// ---------------------------------------------------------------------------
// Fused prep kernel: conv1 | convW x3 | mixgate | rope table
// ---------------------------------------------------------------------------
#define NB_CONV1 (Tn*DIMn/4/256)   // 8192
#define NB_WQ   1024
#define NB_WKV  2048
#define NB_WO   1024
#define NB_MIX  64
#define NB_TAB  (Sn*32/256)        // 256
#define NB_PREP (NB_CONV1+NB_WQ+NB_WKV+NB_WO+NB_MIX+NB_TAB)
#define PREP_SMEM (128*65*4 + 64*32*4)

__global__ void __launch_bounds__(256) prep(
    const float* __restrict__ tokens,
    const float* __restrict__ Wq, const float* __restrict__ Wkv,
    const float* __restrict__ Wout,
    const float* __restrict__ Wmix, const float* __restrict__ Wgate,
    ush* __restrict__ tok, ush* __restrict__ wall, ush* __restrict__ wo,
    float* __restrict__ gmix, float* __restrict__ ggate,
    float2* __restrict__ rope)
{
    extern __shared__ char ps[];
    int blk = blockIdx.x;
    const int tid = threadIdx.x;

    if (blk < NB_CONV1) {
        int i = blk * 256 + tid;
        float4 v = ((const float4*)tokens)[i];
        ((uint2*)tok)[i] = make_uint2(packh(v.x, v.y), packh(v.z, v.w));
        return;
    }
    blk -= NB_CONV1;

    if (blk < NB_WQ + NB_WKV + NB_WO) {
        const float* W; ush* T; int N;
        if (blk < NB_WQ)               { W = Wq;   T = wall;               N = 1024; }
        else if (blk < NB_WQ + NB_WKV) { W = Wkv;  T = wall + 1024 * 1024; N = 2048; blk -= NB_WQ; }
        else                           { W = Wout; T = wo;                 N = 1024; blk -= NB_WQ + NB_WKV; }
        float (*t)[33] = (float(*)[33])ps;
        int ntiles = N / 32;
        int n0 = (blk % ntiles) * 32, k0 = (blk / ntiles) * 32;
        int tx = tid & 31, ty = tid >> 5;
#pragma unroll
        for (int r = 0; r < 4; r++)
            t[ty + 8 * r][tx] = W[(size_t)(k0 + ty + 8 * r) * N + n0 + tx];
        __syncthreads();
#pragma unroll
        for (int r = 0; r < 4; r++) {
            float v = t[tx][ty + 8 * r];
            __half hb = __float2half_rn(v);
            T[(size_t)(n0 + ty + 8 * r) * 1024 + k0 + tx] = *reinterpret_cast<ush*>(&hb);
        }
        return;
    }
    blk -= NB_WQ + NB_WKV + NB_WO;

    if (blk < NB_MIX) {
        float* Ts = (float*)ps;
        float* Ws = Ts + 128 * 65;
        const int row0 = blk * 128;
        const int r  = tid >> 1;
        const int cg = (tid & 1) << 4;

        float acc[16];
#pragma unroll
        for (int c = 0; c < 16; c++) acc[c] = 0.f;

        for (int k0 = 0; k0 < 1024; k0 += 64) {
#pragma unroll
            for (int u = 0; u < 8; u++) {
                int fi = tid + u * 256;
                int rr = fi >> 4;
                int cc = (fi & 15) << 2;
                float4 x = *(const float4*)(tokens + (size_t)(row0 + rr) * 1024 + k0 + cc);
                Ts[rr * 65 + cc]     = x.x;
                Ts[rr * 65 + cc + 1] = x.y;
                Ts[rr * 65 + cc + 2] = x.z;
                Ts[rr * 65 + cc + 3] = x.w;
            }
#pragma unroll
            for (int u = 0; u < 8; u++) {
                int fi = tid + u * 256;
                int rr = fi >> 5;
                int cc = fi & 31;
                Ws[rr * 32 + cc] = (cc < 16) ? Wmix[(k0 + rr) * 16 + cc]
                                             : Wgate[(k0 + rr) * 16 + (cc - 16)];
            }
            __syncthreads();
            for (int kk = 0; kk < 64; kk++) {
                float a = Ts[r * 65 + kk];
#pragma unroll
                for (int c = 0; c < 16; c++) acc[c] += a * Ws[kk * 32 + cg + c];
            }
            __syncthreads();
        }

        const int t = row0 + r;
#pragma unroll
        for (int c = 0; c < 16; c++) {
            float sg = 1.0f / (1.0f + expf(-acc[c]));
            int col = cg + c;
            if (col < 16) gmix[t * 16 + col] = sg;
            else          ggate[t * 16 + (col - 16)] = sg;
        }
        return;
    }
    blk -= NB_MIX;

    {
        const float L2F = 13.2877123795494f / 32.0f;
        int idx = blk * 256 + tid;
        int s = idx >> 5, i = idx & 31;
        float inv = exp2f(-(float)i * L2F);
        float ang = (float)s * inv;
        float sn, cs;
        sincosf(ang, &sn, &cs);
        rope[idx] = make_float2(cs, sn);
    }
}

// ---------------------------------------------------------------------------
// fp16 GEMM (round-14 config): CTA 128x128, 256 thr, 8 warps (4m x 2n),
// warp 32x64, K-chunk 64, 3-stage cp.async, 2 CTA/SM.
// mode 0: fp32 C store. mode 1: fused QKV epilogue (rope table / v-mix).
// ---------------------------------------------------------------------------
#define PADE 72
#define KIND_ELEMS (128*PADE)
#define STAGE_ELEMS (2*KIND_ELEMS)
#define NSTAGE 3
#define NCHUNK 16
#define GEMM_SMEM (NSTAGE*STAGE_ELEMS*2)

__global__ void __launch_bounds__(256, 2) gemm_mma(
    const ush* __restrict__ Ah, const ush* __restrict__ Bh,
    float* __restrict__ C,
    ush* __restrict__ qs, ush* __restrict__ ks, ush* __restrict__ vs,
    const float* __restrict__ vres, const float* __restrict__ mix,
    const float2* __restrict__ rope,
    int mode)
{
    extern __shared__ ush sh[];
    const int tid  = threadIdx.x;
    const int wid  = tid >> 5, lane = tid & 31;
    const int brow = blockIdx.y * 128, bcol = blockIdx.x * 128;
    const int wm   = (wid & 3) * 32;
    const int wn   = (wid >> 2) * 64;
    const int K    = 1024;

    const uint32_t sbase = smem_u32(sh);

    float acc[2][8][4];
#pragma unroll
    for (int i = 0; i < 2; i++)
#pragma unroll
        for (int j = 0; j < 8; j++)
#pragma unroll
            for (int k = 0; k < 4; k++) acc[i][j][k] = 0.f;

    const ush* srcs[2] = {Ah, Bh};
    const int rbase[2] = {brow, bcol};

    auto cp_chunk = [&](int cidx) {
        int k0 = cidx * 64;
        int st = cidx % NSTAGE;
#pragma unroll
        for (int kind = 0; kind < 2; kind++) {
#pragma unroll
            for (int q = 0; q < 4; q++) {
                int e = tid + q * 256;
                int row = e >> 3, ce = (e & 7) * 8;
                const ush* g = srcs[kind] + (size_t)(rbase[kind] + row) * K + k0 + ce;
                uint32_t d = sbase + (uint32_t)(st * STAGE_ELEMS + kind * KIND_ELEMS +
                                                row * PADE + ce) * 2;
                cp16(d, g);
            }
        }
        asm volatile("cp.async.commit_group;" ::: "memory");
    };

    cp_chunk(0); cp_chunk(1);

    for (int c = 0; c < NCHUNK; c++) {
        asm volatile("cp.async.wait_group 1;" ::: "memory");
        __syncthreads();
        if (c + 2 < NCHUNK) cp_chunk(c + 2);
        else asm volatile("cp.async.commit_group;" ::: "memory");

        uint32_t abase = sbase + (uint32_t)(c % NSTAGE) * STAGE_ELEMS * 2;

#pragma unroll
        for (int ksub = 0; ksub < 4; ksub++) {
            uint32_t a[2][4];
            {
                int arow = wm + (lane & 15);
                int acol = ksub * 16 + (lane >> 4) * 8;
#pragma unroll
                for (int ms = 0; ms < 2; ms++)
                    ldsm4(a[ms], abase + (uint32_t)((arow + ms * 16) * PADE + acol) * 2);
            }
            uint32_t b[8][2];
            {
                int bn = (lane & 7) | ((lane >> 1) & 8);
                int bk = ksub * 16 + ((lane >> 3) & 1) * 8;
#pragma unroll
                for (int g = 0; g < 4; g++) {
                    uint32_t r[4];
                    ldsm4(r, abase + (uint32_t)(KIND_ELEMS +
                          (wn + g * 16 + bn) * PADE + bk) * 2);
                    b[2 * g][0]     = r[0]; b[2 * g][1]     = r[1];
                    b[2 * g + 1][0] = r[2]; b[2 * g + 1][1] = r[3];
                }
            }
#pragma unroll
            for (int ms = 0; ms < 2; ms++)
#pragma unroll
                for (int nf = 0; nf < 8; nf++)
                    mma16816h(acc[ms][nf], a[ms], b[nf]);
        }
        __syncthreads();
    }

    if (mode == 0) {
#pragma unroll
        for (int ms = 0; ms < 2; ms++) {
            int r0 = brow + wm + ms * 16 + (lane >> 2);
#pragma unroll
            for (int nf = 0; nf < 8; nf++) {
                int cc = bcol + wn + nf * 8 + 2 * (lane & 3);
                *(float2*)(C + (size_t)r0 * 1024 + cc)       = make_float2(acc[ms][nf][0], acc[ms][nf][1]);
                *(float2*)(C + (size_t)(r0 + 8) * 1024 + cc) = make_float2(acc[ms][nf][2], acc[ms][nf][3]);
            }
        }
        return;
    }

    // fused QKV epilogue: seg 0=q (rope, scale 0.125*log2e), 1=k (rope), 2=v (mix)
    const int seg  = bcol >> 10;
    const int colb = (bcol & 1023) + wn + 2 * (lane & 3);
    ush* dst = (seg == 0) ? qs : (seg == 1) ? ks : vs;
    const float qscale = (seg == 0) ? 0.125f * 1.4426950408889634f : 1.0f;

#pragma unroll
    for (int ms = 0; ms < 2; ms++) {
        int r0 = brow + wm + ms * 16 + (lane >> 2);
#pragma unroll
        for (int half = 0; half < 2; half++) {
            int row = r0 + half * 8;
            int s = row & (Sn - 1);
            int bb = row >> 11;
#pragma unroll
            for (int nf = 0; nf < 8; nf++) {
                float x0 = acc[ms][nf][half * 2 + 0];
                float x1 = acc[ms][nf][half * 2 + 1];
                int colc = colb + nf * 8;
                size_t o = (size_t)row * 1024 + colc;
                float y0, y1;
                if (seg < 2) {
                    int i = (colc & 63) >> 1;
                    float2 t = rope[(s << 5) + i];
                    y0 = (x0 * t.x - x1 * t.y) * qscale;
                    y1 = (x1 * t.x + x0 * t.y) * qscale;
                } else {
                    int hh = (colc & 1023) >> 6;
                    int d  = colc & 63;
                    float m = mix[row * Hn + hh];
                    const float* rp = vres + (((size_t)bb * Hn + hh) * Sn + s) * Dn + d;
                    float2 rr = *(const float2*)rp;
                    y0 = x0 + (rr.x - x0) * m;
                    y1 = x1 + (rr.y - x1) * m;
                }
                *(uint32_t*)(dst + o) = packh(y0, y1);
            }
        }
    }
}

// ---------------------------------------------------------------------------
// Sliding-window flash attention: 128-query-row CTA (8 warps, 256 thr),
// shared K/V tile stream with per-warp window, fp16, exp2 softmax.
// ---------------------------------------------------------------------------
#define APAD 72
#define QARR (128*APAD)
#define KARR (64*APAD)
#define ATT_SMEM ((QARR + 4*KARR)*2)   // Q, K0, V0, K1, V1

__global__ void __launch_bounds__(256) attn_mma(
    const ush* __restrict__ qs, const ush* __restrict__ kh,
    const ush* __restrict__ vh, const float* __restrict__ gate,
    ush* __restrict__ ao)
{
    extern __shared__ ush smA[];
    ush* Qs = smA;

    const int b = blockIdx.z, h = blockIdx.y, q0 = blockIdx.x * 128;
    const int tid = threadIdx.x, wid = tid >> 5, lane = tid & 31;
    const int wm = wid * 16;            // warp's 16 rows at q0+wm
    const size_t bbase = (size_t)b * Sn;
    const int hoff = h * Dn;

    const uint32_t sb = smem_u32(Qs);
    const int wr = q0 + wm;
    const int wlo = (wr >= WIN) ? ((wr - WIN) >> 6) : 0;
    const int whi = wr >> 6;
    const int ct_lo = (q0 >= WIN) ? ((q0 - WIN) >> 6) : 0;
    const int ct_hi = (q0 + 127) >> 6;

    auto cp_kv = [&](int jt, int buf) {
        int j0 = jt * 64;
        const ush* kg = kh + (bbase + j0) * (size_t)HDn + hoff;
        const ush* vg = vh + (bbase + j0) * (size_t)HDn + hoff;
        uint32_t kd = sb + (uint32_t)(QARR + 2 * buf * KARR) * 2;
        uint32_t vd = kd + (uint32_t)KARR * 2;
#pragma unroll
        for (int i = 0; i < 2; i++) {
            int e = tid + i * 256;      // 512 chunks per array
            int row = e >> 3, c = (e & 7) * 8;
            cp16(kd + (uint32_t)(row * APAD + c) * 2, kg + (size_t)row * HDn + c);
            cp16(vd + (uint32_t)(row * APAD + c) * 2, vg + (size_t)row * HDn + c);
        }
        asm volatile("cp.async.commit_group;" ::: "memory");
    };

    // prefetch first K/V tile, then load Q (128 rows)
    cp_kv(ct_lo, 0);
#pragma unroll
    for (int i = 0; i < 4; i++) {
        int e = tid + i * 256;          // 1024 chunks
        int row = e >> 3, c = (e & 7) * 8;
        size_t g = (bbase + q0 + row) * (size_t)HDn + hoff + c;
        *(uint4*)(Qs + row * APAD + c) = *(const uint4*)(qs + g);
    }
    __syncthreads();

    uint32_t qf[4][4];
    {
        int arow = wm + (lane & 15);
        int ac0  = (lane >> 4) * 8;
#pragma unroll
        for (int ks = 0; ks < 4; ks++)
            ldsm4(qf[ks], sb + (uint32_t)(arow * APAD + ks * 16 + ac0) * 2);
    }

    float mi0 = -1e30f, mi1 = -1e30f, li0 = 0.f, li1 = 0.f;
    float accO[8][4];
#pragma unroll
    for (int i = 0; i < 8; i++)
#pragma unroll
        for (int j = 0; j < 4; j++) accO[i][j] = 0.f;

    const int gi0 = wr + (lane >> 2);
    const int gi1 = gi0 + 8;

    const int bn  = (lane & 7) | ((lane >> 1) & 8);
    const int bk8 = ((lane >> 3) & 1) * 8;
    const int vr0 = lane & 15;
    const int vc8 = (lane >> 4) * 8;

    for (int jt = ct_lo; jt <= ct_hi; jt++) {
        const int j0 = jt * 64;
        const int buf = (jt - ct_lo) & 1;
        asm volatile("cp.async.wait_group 0;" ::: "memory");
        __syncthreads();
        if (jt < ct_hi) cp_kv(jt + 1, buf ^ 1);

        if (jt >= wlo && jt <= whi) {   // warp-uniform branch
            const uint32_t kb = sb + (uint32_t)(QARR + 2 * buf * KARR) * 2;
            const uint32_t vb = kb + (uint32_t)KARR * 2;

            float s[8][4];
#pragma unroll
            for (int i = 0; i < 8; i++)
#pragma unroll
                for (int j = 0; j < 4; j++) s[i][j] = 0.f;

#pragma unroll
            for (int ks = 0; ks < 4; ks++) {
#pragma unroll
                for (int g2 = 0; g2 < 4; g2++) {
                    uint32_t off = (uint32_t)(((g2 * 16 + bn) * APAD + ks * 16 + bk8) * 2);
                    uint32_t rh[4];
                    ldsm4(rh, kb + off);
                    uint32_t bh0[2] = {rh[0], rh[1]}, bh1[2] = {rh[2], rh[3]};
                    mma16816h(s[2*g2],   qf[ks], bh0);
                    mma16816h(s[2*g2+1], qf[ks], bh1);
                }
            }

            if (jt == whi || jt == wlo) {
#pragma unroll
                for (int nf = 0; nf < 8; nf++) {
                    int cbase = j0 + nf * 8 + (lane & 3) * 2;
#pragma unroll
                    for (int jj = 0; jj < 2; jj++) {
                        int gj = cbase + jj;
                        int d0 = gi0 - gj, d1 = gi1 - gj;
                        if (d0 < 0 || d0 > WIN) s[nf][jj]     = -1e30f;
                        if (d1 < 0 || d1 > WIN) s[nf][2 + jj] = -1e30f;
                    }
                }
            }

            float mt0 = -1e30f, mt1 = -1e30f;
#pragma unroll
            for (int nf = 0; nf < 8; nf++) {
                mt0 = fmaxf(mt0, fmaxf(s[nf][0], s[nf][1]));
                mt1 = fmaxf(mt1, fmaxf(s[nf][2], s[nf][3]));
            }
            mt0 = fmaxf(mt0, __shfl_xor_sync(0xffffffffu, mt0, 1));
            mt0 = fmaxf(mt0, __shfl_xor_sync(0xffffffffu, mt0, 2));
            mt1 = fmaxf(mt1, __shfl_xor_sync(0xffffffffu, mt1, 1));
            mt1 = fmaxf(mt1, __shfl_xor_sync(0xffffffffu, mt1, 2));

            float mn0 = fmaxf(mi0, mt0), mn1 = fmaxf(mi1, mt1);
            float f0 = exp2f(mi0 - mn0), f1 = exp2f(mi1 - mn1);
            mi0 = mn0; mi1 = mn1;

            float su0 = 0.f, su1 = 0.f;
#pragma unroll
            for (int nf = 0; nf < 8; nf++) {
                s[nf][0] = exp2f(s[nf][0] - mn0);
                s[nf][1] = exp2f(s[nf][1] - mn0);
                s[nf][2] = exp2f(s[nf][2] - mn1);
                s[nf][3] = exp2f(s[nf][3] - mn1);
                su0 += s[nf][0] + s[nf][1];
                su1 += s[nf][2] + s[nf][3];
            }
            su0 += __shfl_xor_sync(0xffffffffu, su0, 1);
            su0 += __shfl_xor_sync(0xffffffffu, su0, 2);
            su1 += __shfl_xor_sync(0xffffffffu, su1, 1);
            su1 += __shfl_xor_sync(0xffffffffu, su1, 2);
            li0 = li0 * f0 + su0;
            li1 = li1 * f1 + su1;
#pragma unroll
            for (int nf = 0; nf < 8; nf++) {
                accO[nf][0] *= f0; accO[nf][1] *= f0;
                accO[nf][2] *= f1; accO[nf][3] *= f1;
            }

#pragma unroll
            for (int ks = 0; ks < 4; ks++) {
                uint32_t ph[4];
                const float* p0 = s[2 * ks];
                const float* p1 = s[2 * ks + 1];
                ph[0] = packh(p0[0], p0[1]);
                ph[1] = packh(p0[2], p0[3]);
                ph[2] = packh(p1[0], p1[1]);
                ph[3] = packh(p1[2], p1[3]);
#pragma unroll
                for (int g2 = 0; g2 < 4; g2++) {
                    uint32_t off = (uint32_t)(((ks * 16 + vr0) * APAD + g2 * 16 + vc8) * 2);
                    uint32_t rh[4];
                    ldsm4t(rh, vb + off);
                    uint32_t bh0[2] = {rh[0], rh[1]}, bh1[2] = {rh[2], rh[3]};
                    mma16816h(accO[2*g2],   ph, bh0);
                    mma16816h(accO[2*g2+1], ph, bh1);
                }
            }
        }
    }

    float g0 = gate[(bbase + gi0) * Hn + h];
    float g1 = gate[(bbase + gi1) * Hn + h];
    float sc0 = g0 / li0, sc1 = g1 / li1;
#pragma unroll
    for (int nf = 0; nf < 8; nf++) {
        int col = hoff + nf * 8 + (lane & 3) * 2;
        size_t i0 = (bbase + gi0) * (size_t)HDn + col;
        size_t i1 = (bbase + gi1) * (size_t)HDn + col;
        *(uint32_t*)(ao + i0) = packh(accO[nf][0] * sc0, accO[nf][1] * sc0);
        *(uint32_t*)(ao + i1) = packh(accO[nf][2] * sc1, accO[nf][3] * sc1);
    }
}

// ---------------------------------------------------------------------------
extern "C" void kernel_launch(void* const* d_in, const int* in_sizes, int n_in,
                              void* d_out, int out_size)
{
    const float* tokens = (const float*)d_in[0];
    const float* vres   = (const float*)d_in[1];
    const float* Wq     = (const float*)d_in[2];
    const float* Wkv    = (const float*)d_in[3];
    const float* Wout   = (const float*)d_in[4];
    const float* Wgate  = (const float*)d_in[5];
    const float* Wmix   = (const float*)d_in[6];
    float* out = (float*)d_out;

    float *pmix, *pgate;
    float2* prope;
    ush *tk, *ao, *wah, *woh, *qsp, *ksp, *vsp;
    cudaGetSymbolAddress((void**)&pmix, g_mix);
    cudaGetSymbolAddress((void**)&pgate,g_gate);
    cudaGetSymbolAddress((void**)&prope,g_rope);
    cudaGetSymbolAddress((void**)&tk,   g_tok);
    cudaGetSymbolAddress((void**)&ao,   g_ao);
    cudaGetSymbolAddress((void**)&wah,  g_wallh);
    cudaGetSymbolAddress((void**)&woh,  g_woh);
    cudaGetSymbolAddress((void**)&qsp,  g_qs);
    cudaGetSymbolAddress((void**)&ksp,  g_ks);
    cudaGetSymbolAddress((void**)&vsp,  g_vs);

    cudaFuncSetAttribute(prep,     cudaFuncAttributeMaxDynamicSharedMemorySize, PREP_SMEM);
    cudaFuncSetAttribute(gemm_mma, cudaFuncAttributeMaxDynamicSharedMemorySize, GEMM_SMEM);
    cudaFuncSetAttribute(attn_mma, cudaFuncAttributeMaxDynamicSharedMemorySize, ATT_SMEM);

    // 1. fused prep: token cast + weight transposes + mix/gate + rope table
    prep<<<NB_PREP, 256, PREP_SMEM>>>(tokens, Wq, Wkv, Wout, Wmix, Wgate,
                                      tk, wah, woh, pmix, pgate, prope);

    // 2. merged QKV projection with fused rope / v-mix epilogue
    gemm_mma<<<dim3(24, 64), 256, GEMM_SMEM>>>(
        tk, wah, nullptr, qsp, ksp, vsp, vres, pmix, prope, 1);

    // 3. windowed attention (128-row CTAs, shared K/V stream) + gate
    attn_mma<<<dim3(Sn / 128, Hn, Bn), 256, ATT_SMEM>>>(
        qsp, ksp, vsp, pgate, ao);

    // 4. output projection into d_out
    gemm_mma<<<dim3(8, 64), 256, GEMM_SMEM>>>(
        ao, woh, out, nullptr, nullptr, nullptr, nullptr, nullptr, nullptr, 0);
}

// round 17
// speedup vs baseline: 1.1781x; 1.1139x over previous
#include <cuda_runtime.h>
#include <cuda_fp16.h>
#include <math.h>
#include <stdint.h>

// Problem constants
#define Bn 4
#define Sn 2048
#define DIMn 1024
#define Hn 16
#define Dn 64
#define Tn (Bn*Sn)      // 8192 tokens
#define HDn 1024
#define WIN 512

typedef unsigned short ush;

// ---------------------------------------------------------------------------
// Scratch (device globals)
// ---------------------------------------------------------------------------
__device__ float g_logit[Tn*32];          // raw mix(0-15)/gate(16-31) logits
__device__ float2 g_rope[Sn*32];          // (cos, sin) per (s, i)

__device__ ush g_tok[(size_t)Tn*DIMn];    // fp16 tokens
__device__ ush g_ao[(size_t)Tn*HDn];      // fp16 attention output
__device__ ush g_wallh[3072*1024];        // fp16: [Wq|Wk|Wv]^T [N=3072,K=1024]
__device__ ush g_woh[1024*1024];          // fp16: Wout^T
__device__ ush g_qs[(size_t)Tn*HDn];      // fp16 q (post-rope, scaled by 0.125*log2e)
__device__ ush g_ks[(size_t)Tn*HDn];      // fp16 k (post-rope)
__device__ ush g_vs[(size_t)Tn*HDn];      // fp16 v (post-mix)

// ---------------------------------------------------------------------------
// Helpers (base sm_103 target — mma.sync / ldmatrix / cp.async, NO tcgen05)
// ---------------------------------------------------------------------------
__device__ __forceinline__ uint32_t smem_u32(const void* p) {
    uint32_t a;
    asm("{ .reg .u64 t; cvta.to.shared.u64 t, %1; cvt.u32.u64 %0, t; }" : "=r"(a) : "l"(p));
    return a;
}
__device__ __forceinline__ void ldsm4(uint32_t* r, uint32_t addr) {
    asm volatile("ldmatrix.sync.aligned.m8n8.x4.shared.b16 {%0,%1,%2,%3}, [%4];"
                 : "=r"(r[0]), "=r"(r[1]), "=r"(r[2]), "=r"(r[3]) : "r"(addr));
}
__device__ __forceinline__ void ldsm4t(uint32_t* r, uint32_t addr) {
    asm volatile("ldmatrix.sync.aligned.m8n8.x4.trans.shared.b16 {%0,%1,%2,%3}, [%4];"
                 : "=r"(r[0]), "=r"(r[1]), "=r"(r[2]), "=r"(r[3]) : "r"(addr));
}
__device__ __forceinline__ void mma16816h(float* d, const uint32_t* a, const uint32_t* b) {
    asm volatile("mma.sync.aligned.m16n8k16.row.col.f32.f16.f16.f32 "
                 "{%0,%1,%2,%3},{%4,%5,%6,%7},{%8,%9},{%0,%1,%2,%3};"
                 : "+f"(d[0]), "+f"(d[1]), "+f"(d[2]), "+f"(d[3])
                 : "r"(a[0]), "r"(a[1]), "r"(a[2]), "r"(a[3]),
                   "r"(b[0]), "r"(b[1]));
}
__device__ __forceinline__ void cp16(uint32_t smem, const void* g) {
    asm volatile("cp.async.cg.shared.global [%0], [%1], 16;" :: "r"(smem), "l"(g));
}
__device__ __forceinline__ uint32_t packh(float y0, float y1) {
    __half2 h = __floats2half2_rn(y0, y1);
    return *reinterpret_cast<uint32_t*>(&h);
}
__device__ __forceinline__ float sigm(float x) {
    return 1.0f / (1.0f + expf(-x));
}

// ---------------------------------------------------------------------------
// zero kernel for the logit accumulator
// ---------------------------------------------------------------------------
__global__ void zerok(float* __restrict__ p, int n4)
{
    int i = blockIdx.x * blockDim.x + threadIdx.x;
    if (i < n4) ((float4*)p)[i] = make_float4(0.f, 0.f, 0.f, 0.f);
}

// ---------------------------------------------------------------------------
// Fused prep kernel: conv1 | convW x3 | mixgate(K-split, atomic) | rope table
// ---------------------------------------------------------------------------
#define NB_CONV1 (Tn*DIMn/4/256)   // 8192
#define NB_WQ   1024
#define NB_WKV  2048
#define NB_WO   1024
#define NB_MIX  512                // 64 row-groups x 8 K-slices
#define NB_TAB  (Sn*32/256)        // 256
#define NB_PREP (NB_CONV1+NB_WQ+NB_WKV+NB_WO+NB_MIX+NB_TAB)
#define PREP_SMEM (128*65*4 + 64*32*4)

__global__ void __launch_bounds__(256) prep(
    const float* __restrict__ tokens,
    const float* __restrict__ Wq, const float* __restrict__ Wkv,
    const float* __restrict__ Wout,
    const float* __restrict__ Wmix, const float* __restrict__ Wgate,
    ush* __restrict__ tok, ush* __restrict__ wall, ush* __restrict__ wo,
    float* __restrict__ logit, float2* __restrict__ rope)
{
    extern __shared__ char ps[];
    int blk = blockIdx.x;
    const int tid = threadIdx.x;

    if (blk < NB_CONV1) {
        int i = blk * 256 + tid;
        float4 v = ((const float4*)tokens)[i];
        ((uint2*)tok)[i] = make_uint2(packh(v.x, v.y), packh(v.z, v.w));
        return;
    }
    blk -= NB_CONV1;

    if (blk < NB_WQ + NB_WKV + NB_WO) {
        const float* W; ush* T; int N;
        if (blk < NB_WQ)               { W = Wq;   T = wall;               N = 1024; }
        else if (blk < NB_WQ + NB_WKV) { W = Wkv;  T = wall + 1024 * 1024; N = 2048; blk -= NB_WQ; }
        else                           { W = Wout; T = wo;                 N = 1024; blk -= NB_WQ + NB_WKV; }
        float (*t)[33] = (float(*)[33])ps;
        int ntiles = N / 32;
        int n0 = (blk % ntiles) * 32, k0 = (blk / ntiles) * 32;
        int tx = tid & 31, ty = tid >> 5;
#pragma unroll
        for (int r = 0; r < 4; r++)
            t[ty + 8 * r][tx] = W[(size_t)(k0 + ty + 8 * r) * N + n0 + tx];
        __syncthreads();
#pragma unroll
        for (int r = 0; r < 4; r++) {
            float v = t[tx][ty + 8 * r];
            __half hb = __float2half_rn(v);
            T[(size_t)(n0 + ty + 8 * r) * 1024 + k0 + tx] = *reinterpret_cast<ush*>(&hb);
        }
        return;
    }
    blk -= NB_WQ + NB_WKV + NB_WO;

    if (blk < NB_MIX) {
        float* Ts = (float*)ps;           // [128][65]
        float* Ws = Ts + 128 * 65;        // [64][32]
        const int row0 = (blk >> 3) * 128;
        const int ks0  = (blk & 7) * 128;
        const int r  = tid >> 1;
        const int cg = (tid & 1) << 4;

        float acc[16];
#pragma unroll
        for (int c = 0; c < 16; c++) acc[c] = 0.f;

        for (int k0 = ks0; k0 < ks0 + 128; k0 += 64) {
#pragma unroll
            for (int u = 0; u < 8; u++) {
                int fi = tid + u * 256;
                int rr = fi >> 4;
                int cc = (fi & 15) << 2;
                float4 x = *(const float4*)(tokens + (size_t)(row0 + rr) * 1024 + k0 + cc);
                Ts[rr * 65 + cc]     = x.x;
                Ts[rr * 65 + cc + 1] = x.y;
                Ts[rr * 65 + cc + 2] = x.z;
                Ts[rr * 65 + cc + 3] = x.w;
            }
#pragma unroll
            for (int u = 0; u < 8; u++) {
                int fi = tid + u * 256;
                int rr = fi >> 5;
                int cc = fi & 31;
                Ws[rr * 32 + cc] = (cc < 16) ? Wmix[(k0 + rr) * 16 + cc]
                                             : Wgate[(k0 + rr) * 16 + (cc - 16)];
            }
            __syncthreads();
            for (int kk = 0; kk < 64; kk++) {
                float a = Ts[r * 65 + kk];
#pragma unroll
                for (int c = 0; c < 16; c++) acc[c] += a * Ws[kk * 32 + cg + c];
            }
            __syncthreads();
        }

        const int t = row0 + r;
#pragma unroll
        for (int c = 0; c < 16; c++)
            atomicAdd(&logit[t * 32 + cg + c], acc[c]);
        return;
    }
    blk -= NB_MIX;

    {
        const float L2F = 13.2877123795494f / 32.0f;
        int idx = blk * 256 + tid;
        int s = idx >> 5, i = idx & 31;
        float inv = exp2f(-(float)i * L2F);
        float ang = (float)s * inv;
        float sn, cs;
        sincosf(ang, &sn, &cs);
        rope[idx] = make_float2(cs, sn);
    }
}

// ---------------------------------------------------------------------------
// fp16 GEMM: CTA 128x128, 256 thr, 8 warps (4m x 2n), warp 32x64,
// K-chunk 64, 3-stage cp.async, 2 CTA/SM.
// mode 0: fp32 C store. mode 1: fused QKV epilogue (rope table / v-mix).
// ---------------------------------------------------------------------------
#define PADE 72
#define KIND_ELEMS (128*PADE)
#define STAGE_ELEMS (2*KIND_ELEMS)
#define NSTAGE 3
#define NCHUNK 16
#define GEMM_SMEM (NSTAGE*STAGE_ELEMS*2)

__global__ void __launch_bounds__(256, 2) gemm_mma(
    const ush* __restrict__ Ah, const ush* __restrict__ Bh,
    float* __restrict__ C,
    ush* __restrict__ qs, ush* __restrict__ ks, ush* __restrict__ vs,
    const float* __restrict__ vres, const float* __restrict__ logit,
    const float2* __restrict__ rope,
    int mode)
{
    extern __shared__ ush sh[];
    const int tid  = threadIdx.x;
    const int wid  = tid >> 5, lane = tid & 31;
    const int brow = blockIdx.y * 128, bcol = blockIdx.x * 128;
    const int wm   = (wid & 3) * 32;
    const int wn   = (wid >> 2) * 64;
    const int K    = 1024;

    const uint32_t sbase = smem_u32(sh);

    float acc[2][8][4];
#pragma unroll
    for (int i = 0; i < 2; i++)
#pragma unroll
        for (int j = 0; j < 8; j++)
#pragma unroll
            for (int k = 0; k < 4; k++) acc[i][j][k] = 0.f;

    const ush* srcs[2] = {Ah, Bh};
    const int rbase[2] = {brow, bcol};

    auto cp_chunk = [&](int cidx) {
        int k0 = cidx * 64;
        int st = cidx % NSTAGE;
#pragma unroll
        for (int kind = 0; kind < 2; kind++) {
#pragma unroll
            for (int q = 0; q < 4; q++) {
                int e = tid + q * 256;
                int row = e >> 3, ce = (e & 7) * 8;
                const ush* g = srcs[kind] + (size_t)(rbase[kind] + row) * K + k0 + ce;
                uint32_t d = sbase + (uint32_t)(st * STAGE_ELEMS + kind * KIND_ELEMS +
                                                row * PADE + ce) * 2;
                cp16(d, g);
            }
        }
        asm volatile("cp.async.commit_group;" ::: "memory");
    };

    cp_chunk(0); cp_chunk(1);

    for (int c = 0; c < NCHUNK; c++) {
        asm volatile("cp.async.wait_group 1;" ::: "memory");
        __syncthreads();
        if (c + 2 < NCHUNK) cp_chunk(c + 2);
        else asm volatile("cp.async.commit_group;" ::: "memory");

        uint32_t abase = sbase + (uint32_t)(c % NSTAGE) * STAGE_ELEMS * 2;

#pragma unroll
        for (int ksub = 0; ksub < 4; ksub++) {
            uint32_t a[2][4];
            {
                int arow = wm + (lane & 15);
                int acol = ksub * 16 + (lane >> 4) * 8;
#pragma unroll
                for (int ms = 0; ms < 2; ms++)
                    ldsm4(a[ms], abase + (uint32_t)((arow + ms * 16) * PADE + acol) * 2);
            }
            uint32_t b[8][2];
            {
                int bn = (lane & 7) | ((lane >> 1) & 8);
                int bk = ksub * 16 + ((lane >> 3) & 1) * 8;
#pragma unroll
                for (int g = 0; g < 4; g++) {
                    uint32_t r[4];
                    ldsm4(r, abase + (uint32_t)(KIND_ELEMS +
                          (wn + g * 16 + bn) * PADE + bk) * 2);
                    b[2 * g][0]     = r[0]; b[2 * g][1]     = r[1];
                    b[2 * g + 1][0] = r[2]; b[2 * g + 1][1] = r[3];
                }
            }
#pragma unroll
            for (int ms = 0; ms < 2; ms++)
#pragma unroll
                for (int nf = 0; nf < 8; nf++)
                    mma16816h(acc[ms][nf], a[ms], b[nf]);
        }
        __syncthreads();
    }

    if (mode == 0) {
#pragma unroll
        for (int ms = 0; ms < 2; ms++) {
            int r0 = brow + wm + ms * 16 + (lane >> 2);
#pragma unroll
            for (int nf = 0; nf < 8; nf++) {
                int cc = bcol + wn + nf * 8 + 2 * (lane & 3);
                *(float2*)(C + (size_t)r0 * 1024 + cc)       = make_float2(acc[ms][nf][0], acc[ms][nf][1]);
                *(float2*)(C + (size_t)(r0 + 8) * 1024 + cc) = make_float2(acc[ms][nf][2], acc[ms][nf][3]);
            }
        }
        return;
    }

    // fused QKV epilogue: seg 0=q (rope, scale 0.125*log2e), 1=k (rope), 2=v (mix)
    const int seg  = bcol >> 10;
    const int colb = (bcol & 1023) + wn + 2 * (lane & 3);
    ush* dst = (seg == 0) ? qs : (seg == 1) ? ks : vs;
    const float qscale = (seg == 0) ? 0.125f * 1.4426950408889634f : 1.0f;

#pragma unroll
    for (int ms = 0; ms < 2; ms++) {
        int r0 = brow + wm + ms * 16 + (lane >> 2);
#pragma unroll
        for (int half = 0; half < 2; half++) {
            int row = r0 + half * 8;
            int s = row & (Sn - 1);
            int bb = row >> 11;
#pragma unroll
            for (int nf = 0; nf < 8; nf++) {
                float x0 = acc[ms][nf][half * 2 + 0];
                float x1 = acc[ms][nf][half * 2 + 1];
                int colc = colb + nf * 8;
                size_t o = (size_t)row * 1024 + colc;
                float y0, y1;
                if (seg < 2) {
                    int i = (colc & 63) >> 1;
                    float2 t = rope[(s << 5) + i];
                    y0 = (x0 * t.x - x1 * t.y) * qscale;
                    y1 = (x1 * t.x + x0 * t.y) * qscale;
                } else {
                    int hh = (colc & 1023) >> 6;
                    int d  = colc & 63;
                    float m = sigm(logit[row * 32 + hh]);
                    const float* rp = vres + (((size_t)bb * Hn + hh) * Sn + s) * Dn + d;
                    float2 rr = *(const float2*)rp;
                    y0 = x0 + (rr.x - x0) * m;
                    y1 = x1 + (rr.y - x1) * m;
                }
                *(uint32_t*)(dst + o) = packh(y0, y1);
            }
        }
    }
}

// ---------------------------------------------------------------------------
// Sliding-window flash attention (round-14 config): 64-query-row CTA,
// 4 warps, fp16, exp2 softmax, cp.async double-buffered K/V tiles.
// ---------------------------------------------------------------------------
#define APAD 72
#define AARR (64*APAD)
#define ATT_SMEM (5*AARR*2)   // Q, K0, V0, K1, V1

__global__ void __launch_bounds__(128) attn_mma(
    const ush* __restrict__ qs, const ush* __restrict__ kh,
    const ush* __restrict__ vh, const float* __restrict__ logit,
    ush* __restrict__ ao)
{
    extern __shared__ ush smA[];
    ush* Qs = smA;

    const int b = blockIdx.z, h = blockIdx.y, q0 = blockIdx.x * 64;
    const int tid = threadIdx.x, wid = tid >> 5, lane = tid & 31;
    const int wm = wid * 16;
    const size_t bbase = (size_t)b * Sn;
    const int hoff = h * Dn;

    const uint32_t sb = smem_u32(Qs);
    const int jt_lo = (q0 >= WIN) ? ((q0 - WIN) >> 6) : 0;
    const int jt_hi = q0 >> 6;

    auto cp_kv = [&](int jt, int buf) {
        int j0 = jt * 64;
        const ush* kg = kh + (bbase + j0) * (size_t)HDn + hoff;
        const ush* vg = vh + (bbase + j0) * (size_t)HDn + hoff;
        uint32_t kd = sb + (uint32_t)((1 + 2 * buf) * AARR) * 2;
        uint32_t vd = kd + (uint32_t)AARR * 2;
#pragma unroll
        for (int i = 0; i < 4; i++) {
            int e = tid + i * 128;
            int row = e >> 3, c = (e & 7) * 8;
            cp16(kd + (uint32_t)(row * APAD + c) * 2, kg + (size_t)row * HDn + c);
            cp16(vd + (uint32_t)(row * APAD + c) * 2, vg + (size_t)row * HDn + c);
        }
        asm volatile("cp.async.commit_group;" ::: "memory");
    };

    cp_kv(jt_lo, 0);
#pragma unroll
    for (int i = 0; i < 4; i++) {
        int e = tid + i * 128;
        int row = e >> 3, c = (e & 7) * 8;
        size_t g = (bbase + q0 + row) * (size_t)HDn + hoff + c;
        *(uint4*)(Qs + row * APAD + c) = *(const uint4*)(qs + g);
    }
    __syncthreads();

    uint32_t qf[4][4];
    {
        int arow = wm + (lane & 15);
        int ac0  = (lane >> 4) * 8;
#pragma unroll
        for (int ks = 0; ks < 4; ks++)
            ldsm4(qf[ks], sb + (uint32_t)(arow * APAD + ks * 16 + ac0) * 2);
    }

    float mi0 = -1e30f, mi1 = -1e30f, li0 = 0.f, li1 = 0.f;
    float accO[8][4];
#pragma unroll
    for (int i = 0; i < 8; i++)
#pragma unroll
        for (int j = 0; j < 4; j++) accO[i][j] = 0.f;

    const int gi0 = q0 + wm + (lane >> 2);
    const int gi1 = gi0 + 8;

    const int bn  = (lane & 7) | ((lane >> 1) & 8);
    const int bk8 = ((lane >> 3) & 1) * 8;
    const int vr0 = lane & 15;
    const int vc8 = (lane >> 4) * 8;

    for (int jt = jt_lo; jt <= jt_hi; jt++) {
        const int j0 = jt * 64;
        const int buf = (jt - jt_lo) & 1;
        asm volatile("cp.async.wait_group 0;" ::: "memory");
        __syncthreads();
        if (jt < jt_hi) cp_kv(jt + 1, buf ^ 1);

        const uint32_t kb = sb + (uint32_t)((1 + 2 * buf) * AARR) * 2;
        const uint32_t vb = kb + (uint32_t)AARR * 2;

        float s[8][4];
#pragma unroll
        for (int i = 0; i < 8; i++)
#pragma unroll
            for (int j = 0; j < 4; j++) s[i][j] = 0.f;

#pragma unroll
        for (int ks = 0; ks < 4; ks++) {
#pragma unroll
            for (int g2 = 0; g2 < 4; g2++) {
                uint32_t off = (uint32_t)(((g2 * 16 + bn) * APAD + ks * 16 + bk8) * 2);
                uint32_t rh[4];
                ldsm4(rh, kb + off);
                uint32_t bh0[2] = {rh[0], rh[1]}, bh1[2] = {rh[2], rh[3]};
                mma16816h(s[2*g2],   qf[ks], bh0);
                mma16816h(s[2*g2+1], qf[ks], bh1);
            }
        }

        if (jt == jt_hi || (jt == jt_lo && q0 >= WIN)) {
#pragma unroll
            for (int nf = 0; nf < 8; nf++) {
                int cbase = j0 + nf * 8 + (lane & 3) * 2;
#pragma unroll
                for (int jj = 0; jj < 2; jj++) {
                    int gj = cbase + jj;
                    int d0 = gi0 - gj, d1 = gi1 - gj;
                    if (d0 < 0 || d0 > WIN) s[nf][jj]     = -1e30f;
                    if (d1 < 0 || d1 > WIN) s[nf][2 + jj] = -1e30f;
                }
            }
        }

        float mt0 = -1e30f, mt1 = -1e30f;
#pragma unroll
        for (int nf = 0; nf < 8; nf++) {
            mt0 = fmaxf(mt0, fmaxf(s[nf][0], s[nf][1]));
            mt1 = fmaxf(mt1, fmaxf(s[nf][2], s[nf][3]));
        }
        mt0 = fmaxf(mt0, __shfl_xor_sync(0xffffffffu, mt0, 1));
        mt0 = fmaxf(mt0, __shfl_xor_sync(0xffffffffu, mt0, 2));
        mt1 = fmaxf(mt1, __shfl_xor_sync(0xffffffffu, mt1, 1));
        mt1 = fmaxf(mt1, __shfl_xor_sync(0xffffffffu, mt1, 2));

        float mn0 = fmaxf(mi0, mt0), mn1 = fmaxf(mi1, mt1);
        float f0 = exp2f(mi0 - mn0), f1 = exp2f(mi1 - mn1);
        mi0 = mn0; mi1 = mn1;

        float su0 = 0.f, su1 = 0.f;
#pragma unroll
        for (int nf = 0; nf < 8; nf++) {
            s[nf][0] = exp2f(s[nf][0] - mn0);
            s[nf][1] = exp2f(s[nf][1] - mn0);
            s[nf][2] = exp2f(s[nf][2] - mn1);
            s[nf][3] = exp2f(s[nf][3] - mn1);
            su0 += s[nf][0] + s[nf][1];
            su1 += s[nf][2] + s[nf][3];
        }
        su0 += __shfl_xor_sync(0xffffffffu, su0, 1);
        su0 += __shfl_xor_sync(0xffffffffu, su0, 2);
        su1 += __shfl_xor_sync(0xffffffffu, su1, 1);
        su1 += __shfl_xor_sync(0xffffffffu, su1, 2);
        li0 = li0 * f0 + su0;
        li1 = li1 * f1 + su1;
#pragma unroll
        for (int nf = 0; nf < 8; nf++) {
            accO[nf][0] *= f0; accO[nf][1] *= f0;
            accO[nf][2] *= f1; accO[nf][3] *= f1;
        }

#pragma unroll
        for (int ks = 0; ks < 4; ks++) {
            uint32_t ph[4];
            const float* p0 = s[2 * ks];
            const float* p1 = s[2 * ks + 1];
            ph[0] = packh(p0[0], p0[1]);
            ph[1] = packh(p0[2], p0[3]);
            ph[2] = packh(p1[0], p1[1]);
            ph[3] = packh(p1[2], p1[3]);
#pragma unroll
            for (int g2 = 0; g2 < 4; g2++) {
                uint32_t off = (uint32_t)(((ks * 16 + vr0) * APAD + g2 * 16 + vc8) * 2);
                uint32_t rh[4];
                ldsm4t(rh, vb + off);
                uint32_t bh0[2] = {rh[0], rh[1]}, bh1[2] = {rh[2], rh[3]};
                mma16816h(accO[2*g2],   ph, bh0);
                mma16816h(accO[2*g2+1], ph, bh1);
            }
        }
    }

    float g0 = sigm(logit[(bbase + gi0) * 32 + 16 + h]);
    float g1 = sigm(logit[(bbase + gi1) * 32 + 16 + h]);
    float sc0 = g0 / li0, sc1 = g1 / li1;
#pragma unroll
    for (int nf = 0; nf < 8; nf++) {
        int col = hoff + nf * 8 + (lane & 3) * 2;
        size_t i0 = (bbase + gi0) * (size_t)HDn + col;
        size_t i1 = (bbase + gi1) * (size_t)HDn + col;
        *(uint32_t*)(ao + i0) = packh(accO[nf][0] * sc0, accO[nf][1] * sc0);
        *(uint32_t*)(ao + i1) = packh(accO[nf][2] * sc1, accO[nf][3] * sc1);
    }
}

// ---------------------------------------------------------------------------
extern "C" void kernel_launch(void* const* d_in, const int* in_sizes, int n_in,
                              void* d_out, int out_size)
{
    const float* tokens = (const float*)d_in[0];
    const float* vres   = (const float*)d_in[1];
    const float* Wq     = (const float*)d_in[2];
    const float* Wkv    = (const float*)d_in[3];
    const float* Wout   = (const float*)d_in[4];
    const float* Wgate  = (const float*)d_in[5];
    const float* Wmix   = (const float*)d_in[6];
    float* out = (float*)d_out;

    float* plog;
    float2* prope;
    ush *tk, *ao, *wah, *woh, *qsp, *ksp, *vsp;
    cudaGetSymbolAddress((void**)&plog, g_logit);
    cudaGetSymbolAddress((void**)&prope,g_rope);
    cudaGetSymbolAddress((void**)&tk,   g_tok);
    cudaGetSymbolAddress((void**)&ao,   g_ao);
    cudaGetSymbolAddress((void**)&wah,  g_wallh);
    cudaGetSymbolAddress((void**)&woh,  g_woh);
    cudaGetSymbolAddress((void**)&qsp,  g_qs);
    cudaGetSymbolAddress((void**)&ksp,  g_ks);
    cudaGetSymbolAddress((void**)&vsp,  g_vs);

    cudaFuncSetAttribute(prep,     cudaFuncAttributeMaxDynamicSharedMemorySize, PREP_SMEM);
    cudaFuncSetAttribute(gemm_mma, cudaFuncAttributeMaxDynamicSharedMemorySize, GEMM_SMEM);
    cudaFuncSetAttribute(attn_mma, cudaFuncAttributeMaxDynamicSharedMemorySize, ATT_SMEM);

    // 0. zero the logit accumulator
    zerok<<<(Tn * 32 / 4 + 255) / 256, 256>>>(plog, Tn * 32 / 4);

    // 1. fused prep: token cast + weight transposes + mixgate partials + rope
    prep<<<NB_PREP, 256, PREP_SMEM>>>(tokens, Wq, Wkv, Wout, Wmix, Wgate,
                                      tk, wah, woh, plog, prope);

    // 2. merged QKV projection with fused rope / v-mix epilogue
    gemm_mma<<<dim3(24, 64), 256, GEMM_SMEM>>>(
        tk, wah, nullptr, qsp, ksp, vsp, vres, plog, prope, 1);

    // 3. windowed attention (64-row CTAs) + gate
    attn_mma<<<dim3(Sn / 64, Hn, Bn), 128, ATT_SMEM>>>(
        qsp, ksp, vsp, plog, ao);

    // 4. output projection into d_out
    gemm_mma<<<dim3(8, 64), 256, GEMM_SMEM>>>(
        ao, woh, out, nullptr, nullptr, nullptr, nullptr, nullptr, nullptr, 0);
}